// round 10
// baseline (speedup 1.0000x reference)
#include <cuda_runtime.h>
#include <cuda_fp16.h>
#include <math.h>

#define SUB_NO 20
#define T_NO 201
#define E_NO 2000
#define I_NO 500
#define T_DATA 20000

// Output layout: concat of (V[20000], out_filters[40*201], C_syn_e[20*2000], C_syn_i[20*500])
#define OFF_V  0
#define OFF_F  (T_DATA)                   // 20000
#define OFF_CE (OFF_F + 40 * T_NO)        // 28040
#define OFF_CI (OFF_CE + SUB_NO * E_NO)   // 68040

#define PAD 48      // IIR warm-up: r^48 <= 2e-5 rel even at +5sigma tau; tol is 1e-3
#define TSTR 32     // padded table row stride (elements)

// ---------------- scratch ----------------
__device__ __align__(128) __half g_TEh[(E_NO + 1) * TSTR];  // fp16 softmax tables (+ zeroed dummy row)
__device__ __align__(128) __half g_TIh[(I_NO + 1) * TSTR];
__device__ float g_synZe[(PAD + T_DATA) * SUB_NO];          // zero-padded head, then syn_e
__device__ float g_synZi[(PAD + T_DATA) * SUB_NO];
__device__ int   g_done = 0;                                // prep-arrival counter (reset by iirtree)

// param pack
#define P_GAIN  0
#define P_THETA 32
#define P_RE    64
#define P_BE    96
#define P_BDE   128
#define P_C1E   160
#define P_RI    192
#define P_BI    224
#define P_BDI   256
#define P_C1I   288
#define P_VO    320
__device__ float g_par[336];

#define N_PREP (E_NO + I_NO + 40 * T_NO + SUB_NO + 1)   // 10561

// ---------------- prep slice (inlined into spike kernel) ----------------
__device__ void do_prep(int tid,
                        const float* __restrict__ Craw_e,
                        const float* __restrict__ Craw_i,
                        const float* __restrict__ Wsyn,
                        const float* __restrict__ Tausyn,
                        const float* __restrict__ Dsyn,
                        const float* __restrict__ Wsub,
                        const float* __restrict__ Vo,
                        const float* __restrict__ Theta,
                        float* __restrict__ out)
{
    if (tid < PAD * SUB_NO) {
        g_synZe[tid] = 0.f;
        g_synZi[tid] = 0.f;
    }
    if (tid < TSTR) {                      // zero dummy rows (gather padding target)
        g_TEh[E_NO * TSTR + tid] = __float2half(0.f);
        g_TIh[I_NO * TSTR + tid] = __float2half(0.f);
    }

    if (tid < E_NO + I_NO) {
        const float* raw;
        float* o;
        __half* tp;
        int stride, e;
        if (tid < E_NO) { raw = Craw_e; o = out + OFF_CE; tp = g_TEh; stride = E_NO; e = tid; }
        else            { raw = Craw_i; o = out + OFF_CI; tp = g_TIh; stride = I_NO; e = tid - E_NO; }
        float v[SUB_NO];
        float m = -1e30f;
#pragma unroll
        for (int j = 0; j < SUB_NO; ++j) { v[j] = raw[j * stride + e]; m = fmaxf(m, v[j]); }
        float s = 0.f;
#pragma unroll
        for (int j = 0; j < SUB_NO; ++j) { v[j] = expf(v[j] - m); s += v[j]; }
        float inv = 1.f / s;
#pragma unroll
        for (int j = 0; j < SUB_NO; ++j) {
            float w = v[j] * inv;
            o[j * stride + e]  = w;
            tp[e * TSTR + j]   = __float2half(w);
        }
    }

    int f = tid - (E_NO + I_NO);
    if (f >= 0 && f < 40 * T_NO) {
        int row  = f / T_NO;
        int k    = f - row * T_NO;
        int type = row / SUB_NO;
        int s    = row - type * SUB_NO;
        float delta = expf(Dsyn[s * 2 + type]);
        float tau   = expf(Tausyn[s * 2 + type]);
        float w     = expf(Wsyn[s * 2 + type]);
        float tt    = fmaxf((float)k - delta, 0.f) / tau;
        float val   = tt * expf(-tt) * w;
        if (type) val = -val;
        out[OFF_F + row * T_NO + k] = val;
    }

    int p = tid - (E_NO + I_NO + 40 * T_NO);
    if (p >= 0 && p < SUB_NO) {
        g_par[P_GAIN  + p] = expf(Wsub[p]);
        g_par[P_THETA + p] = Theta[p];
#pragma unroll
        for (int type = 0; type < 2; ++type) {
            float delta = expf(Dsyn[p * 2 + type]);
            float tau   = expf(Tausyn[p * 2 + type]);
            float w     = expf(Wsyn[p * 2 + type]);
            float r     = expf(-1.f / tau);
            float B     = w * expf(delta / tau) / tau;
            if (type) B = -B;
            float c1 = (delta > 1.f) ? B * (delta - 1.f) * r : 0.f;
            g_par[(type ? P_RI  : P_RE ) + p] = r;
            g_par[(type ? P_BI  : P_BE ) + p] = B;
            g_par[(type ? P_BDI : P_BDE) + p] = B * delta;
            g_par[(type ? P_C1I : P_C1E) + p] = c1;
        }
    }
    if (tid == N_PREP - 1) g_par[P_VO] = Vo[0];
}

// ---------------- K1: fused prep + scan(E,I) + gather(E,I) ----------------
template<int NFULL, int TAIL, int PF>
__device__ __forceinline__ int row_scan(const float4* __restrict__ Sv, int npad,
                                        ushort* __restrict__ idxb,
                                        int lane, unsigned lt)
{
    constexpr int NT = NFULL + 1;
    const float4 z4 = make_float4(0.f, 0.f, 0.f, 0.f);
    float4 ring[PF];
#pragma unroll
    for (int p = 0; p < PF; ++p) {
        if (p < NT) ring[p] = (p < NFULL || lane < TAIL) ? __ldcs(Sv + p * 32 + lane) : z4;
        else        ring[p] = z4;
    }
    int cnt = 0;
#pragma unroll
    for (int it = 0; it < NT; ++it) {
        float4 v = ring[it % PF];
        if (it + PF < NT)
            ring[it % PF] = ((it + PF) < NFULL || lane < TAIL) ? __ldcs(Sv + (it + PF) * 32 + lane) : z4;
        unsigned m0 = __ballot_sync(0xffffffffu, v.x != 0.f);
        unsigned m1 = __ballot_sync(0xffffffffu, v.y != 0.f);
        unsigned m2 = __ballot_sync(0xffffffffu, v.z != 0.f);
        unsigned m3 = __ballot_sync(0xffffffffu, v.w != 0.f);
        int t0 = __popc(m0), t1 = __popc(m1), t2 = __popc(m2), t3 = __popc(m3);
        int p0 = cnt + __popc(m0 & lt);
        int p1 = cnt + t0 + __popc(m1 & lt);
        int p2 = cnt + t0 + t1 + __popc(m2 & lt);
        int p3 = cnt + t0 + t1 + t2 + __popc(m3 & lt);
        int base = (it * 32 + lane) * 4;
        if (v.x != 0.f) idxb[p0] = (ushort)(base);
        if (v.y != 0.f) idxb[p1] = (ushort)(base + 1);
        if (v.z != 0.f) idxb[p2] = (ushort)(base + 2);
        if (v.w != 0.f) idxb[p3] = (ushort)(base + 3);
        cnt += t0 + t1 + t2 + t3;
    }
    int cpad = (cnt + 7) & ~7;
    if (lane < cpad - cnt) idxb[cnt + lane] = (ushort)npad;  // dummy -> zeroed table row
    return cpad >> 3;
}

// L2-resident fp16 table gather: per nonzero a lane-coalesced 40B row read (2 sectors).
__device__ __forceinline__ float gather_h(const uint4* __restrict__ ib, int nk,
                                          const __half* __restrict__ tab, int jj)
{
    float a0 = 0.f, a1 = 0.f;
#pragma unroll 2
    for (int k = 0; k < nk; ++k) {
        uint4 w = ib[k];
        a0 += __half2float(__ldg(tab + ((w.x & 0xffffu) * TSTR + jj)));
        a1 += __half2float(__ldg(tab + ((w.x >> 16)     * TSTR + jj)));
        a0 += __half2float(__ldg(tab + ((w.y & 0xffffu) * TSTR + jj)));
        a1 += __half2float(__ldg(tab + ((w.y >> 16)     * TSTR + jj)));
        a0 += __half2float(__ldg(tab + ((w.z & 0xffffu) * TSTR + jj)));
        a1 += __half2float(__ldg(tab + ((w.z >> 16)     * TSTR + jj)));
        a0 += __half2float(__ldg(tab + ((w.w & 0xffffu) * TSTR + jj)));
        a1 += __half2float(__ldg(tab + ((w.w >> 16)     * TSTR + jj)));
    }
    return a0 + a1;
}

#define K2_THREADS 256
#define K2_WARPS   8
#define K2_BLOCKS  (148 * 4)   // exactly one wave, all co-resident (spin-safe)
#define IDX_E 272              // ushort slots for E indices (544 B, 16B aligned)
#define IDX_I 96               // ushort slots for I indices

__global__ void __launch_bounds__(K2_THREADS, 4)
spike_kernel(const float* __restrict__ Se, const float* __restrict__ Si,
             const float* __restrict__ Craw_e, const float* __restrict__ Craw_i,
             const float* __restrict__ Wsyn, const float* __restrict__ Tausyn,
             const float* __restrict__ Dsyn, const float* __restrict__ Wsub,
             const float* __restrict__ Vo, const float* __restrict__ Theta,
             float* __restrict__ out)
{
    __shared__ __align__(16) ushort idx_s[K2_WARPS][IDX_E + IDX_I];

    // --- prep slice (each thread handles at most one prep index) ---
    int gtid = blockIdx.x * K2_THREADS + threadIdx.x;
    if (gtid < N_PREP)
        do_prep(gtid, Craw_e, Craw_i, Wsyn, Tausyn, Dsyn, Wsub, Vo, Theta, out);
    __threadfence();
    __syncthreads();
    if (threadIdx.x == 0) atomicAdd(&g_done, 1);

    int warp = threadIdx.x >> 5;
    int lane = threadIdx.x & 31;
    unsigned lt = (1u << lane) - 1u;
    int jj = (lane < SUB_NO) ? lane : 0;
    ushort* idxE = idx_s[warp];
    ushort* idxI = idx_s[warp] + IDX_E;

    int gwarp = blockIdx.x * K2_WARPS + warp;
    bool ready = false;

    for (int row = gwarp; row < T_DATA; row += K2_BLOCKS * K2_WARPS) {
        // ---- scan BOTH rows first: keeps DRAM loads in flight through the gathers ----
        int enk = row_scan<15, 20, 5>((const float4*)(Se + (size_t)row * E_NO), E_NO,
                                      idxE, lane, lt);
        int ink = row_scan<3, 29, 3>((const float4*)(Si + (size_t)row * I_NO), I_NO,
                                     idxI, lane, lt);
        __syncwarp();
        if (!ready) {   // wait once until all blocks' prep slices are visible
            while (*(volatile int*)&g_done < K2_BLOCKS) __nanosleep(200);
            __threadfence();
            ready = true;
        }
        // ---- gathers (L2-resident tables) ----
        float ae = gather_h((const uint4*)idxE, enk, g_TEh, jj);
        float ai = gather_h((const uint4*)idxI, ink, g_TIh, jj);
        __syncwarp();

        if (lane < SUB_NO) {
            g_synZe[(PAD + row) * SUB_NO + lane] = ae;
            g_synZi[(PAD + row) * SUB_NO + lane] = ai;
        }
    }
}

// ---------------- K2: fused IIR + tree (smem staged) ----------------
#define CHU  32
#define NCH  (T_DATA / CHU)    // 625
#define NIT  (PAD + CHU)       // 80, compile-time
#define RD   16
#define PAIRS_PER_BLK 4        // 157 blocks -> uses all 148 SMs
#define IT_THREADS (PAIRS_PER_BLK * 64)  // 256

__device__ __forceinline__ float fast_tanh(float x)
{
    x = fminf(fmaxf(x, -15.f), 15.f);
    float e = __expf(2.f * x);
    return __fdividef(e - 1.f, e + 1.f);
}

__global__ void __launch_bounds__(IT_THREADS)
iirtree_kernel(float* __restrict__ out)
{
    // reset the prep barrier for the next graph replay (this kernel always runs last)
    if (blockIdx.x == 0 && threadIdx.x == 0) g_done = 0;

    __shared__ float syn2[PAIRS_PER_BLK][2][CHU][21];
    int w    = threadIdx.x >> 6;
    int type = (threadIdx.x >> 5) & 1;
    int lane = threadIdx.x & 31;
    int chunk = blockIdx.x * PAIRS_PER_BLK + w;

    if (chunk < NCH && lane < SUB_NO) {
        int s = lane;
        const float* __restrict__ x = (type ? g_synZi : g_synZe) + chunk * CHU * SUB_NO + s;
        float r  = g_par[(type ? P_RI  : P_RE ) + s];
        float B  = g_par[(type ? P_BI  : P_BE ) + s];
        float BD = g_par[(type ? P_BDI : P_BDE) + s];
        float C1 = g_par[(type ? P_C1I : P_C1E) + s];

        float ring[RD];
#pragma unroll
        for (int p = 0; p < RD; ++p) ring[p] = x[p * SUB_NO];

        float s1 = 0.f, s2 = 0.f, xp = 0.f;
#pragma unroll
        for (int k = 0; k < NIT; ++k) {
            float xv = ring[k % RD];
            if (k + RD < NIT) ring[k % RD] = x[(k + RD) * SUB_NO];
            float ns2 = r * (s1 + s2);
            s1 = fmaf(r, s1, xv);
            s2 = ns2;
            if (k >= PAD)
                syn2[w][type][k - PAD][s] = B * s2 - BD * s1 + BD * xv + C1 * xp;
            xp = xv;
        }
    }
    __syncthreads();

    if (chunk < NCH && type == 0) {
        int t = chunk * CHU + lane;
        float syn[SUB_NO];
#pragma unroll
        for (int s = 0; s < SUB_NO; ++s)
            syn[s] = syn2[w][0][lane][s] + syn2[w][1][lane][s];

        float gain[SUB_NO], th[SUB_NO];
#pragma unroll
        for (int j = 0; j < SUB_NO; ++j) { gain[j] = g_par[P_GAIN + j]; th[j] = g_par[P_THETA + j]; }

        float sub[SUB_NO];
#pragma unroll
        for (int i = SUB_NO - 1; i >= 0; --i) {
            float v = syn[i] + th[i];
            if (2 * i + 1 < SUB_NO) v = fmaf(gain[2 * i + 1], sub[2 * i + 1], v);
            if (2 * i + 2 < SUB_NO) v = fmaf(gain[2 * i + 2], sub[2 * i + 2], v);
            sub[i] = fast_tanh(v);
        }
        out[t] = fmaf(sub[0], gain[0], g_par[P_VO]);
    }
}

// ---------------- launch ----------------
extern "C" void kernel_launch(void* const* d_in, const int* in_sizes, int n_in,
                              void* d_out, int out_size)
{
    const float* Se     = (const float*)d_in[0];
    const float* Si     = (const float*)d_in[1];
    const float* Wsyn   = (const float*)d_in[3];
    const float* Tausyn = (const float*)d_in[4];
    const float* Dsyn   = (const float*)d_in[5];
    const float* Wsub   = (const float*)d_in[6];
    const float* Vo     = (const float*)d_in[7];
    const float* Theta  = (const float*)d_in[8];
    const float* Ce     = (const float*)d_in[9];
    const float* Ci     = (const float*)d_in[10];
    float* out = (float*)d_out;

    spike_kernel<<<K2_BLOCKS, K2_THREADS>>>(Se, Si, Ce, Ci, Wsyn, Tausyn, Dsyn,
                                            Wsub, Vo, Theta, out);

    iirtree_kernel<<<(NCH + PAIRS_PER_BLK - 1) / PAIRS_PER_BLK, IT_THREADS>>>(out);
}

// round 11
// speedup vs baseline: 1.0307x; 1.0307x over previous
#include <cuda_runtime.h>
#include <cuda_fp16.h>
#include <math.h>

#define SUB_NO 20
#define T_NO 201
#define E_NO 2000
#define I_NO 500
#define T_DATA 20000

// Output layout: concat of (V[20000], out_filters[40*201], C_syn_e[20*2000], C_syn_i[20*500])
#define OFF_V  0
#define OFF_F  (T_DATA)                   // 20000
#define OFF_CE (OFF_F + 40 * T_NO)        // 28040
#define OFF_CI (OFF_CE + SUB_NO * E_NO)   // 68040

#define PAD 48      // IIR warm-up: r^48 <= 2e-5 rel even at +5sigma tau; tol is 1e-3
#define TSTR 32     // padded table row stride (elements)

// ---------------- scratch ----------------
__device__ __align__(128) __half g_TEh[(E_NO + 1) * TSTR];  // fp16 softmax tables (+ zeroed dummy row)
__device__ __align__(128) __half g_TIh[(I_NO + 1) * TSTR];
__device__ float g_synZe[(PAD + T_DATA) * SUB_NO];          // zero-padded head, then syn_e
__device__ float g_synZi[(PAD + T_DATA) * SUB_NO];
__device__ int   g_A = 0;   // prep barrier
__device__ int   g_B = 0;   // spike-complete barrier
__device__ int   g_C = 0;   // exit counter (last block resets all)

// param pack
#define P_GAIN  0
#define P_THETA 32
#define P_RE    64
#define P_BE    96
#define P_BDE   128
#define P_C1E   160
#define P_RI    192
#define P_BI    224
#define P_BDI   256
#define P_C1I   288
#define P_VO    320
__device__ float g_par[336];

#define N_PREP (E_NO + I_NO + 40 * T_NO + SUB_NO + 1)   // 10561

// ---------------- prep slice ----------------
__device__ void do_prep(int tid,
                        const float* __restrict__ Craw_e,
                        const float* __restrict__ Craw_i,
                        const float* __restrict__ Wsyn,
                        const float* __restrict__ Tausyn,
                        const float* __restrict__ Dsyn,
                        const float* __restrict__ Wsub,
                        const float* __restrict__ Vo,
                        const float* __restrict__ Theta,
                        float* __restrict__ out)
{
    if (tid < PAD * SUB_NO) {
        g_synZe[tid] = 0.f;
        g_synZi[tid] = 0.f;
    }
    if (tid < TSTR) {                      // zero dummy rows (gather padding target)
        g_TEh[E_NO * TSTR + tid] = __float2half(0.f);
        g_TIh[I_NO * TSTR + tid] = __float2half(0.f);
    }

    if (tid < E_NO + I_NO) {
        const float* raw;
        float* o;
        __half* tp;
        int stride, e;
        if (tid < E_NO) { raw = Craw_e; o = out + OFF_CE; tp = g_TEh; stride = E_NO; e = tid; }
        else            { raw = Craw_i; o = out + OFF_CI; tp = g_TIh; stride = I_NO; e = tid - E_NO; }
        float v[SUB_NO];
        float m = -1e30f;
#pragma unroll
        for (int j = 0; j < SUB_NO; ++j) { v[j] = raw[j * stride + e]; m = fmaxf(m, v[j]); }
        float s = 0.f;
#pragma unroll
        for (int j = 0; j < SUB_NO; ++j) { v[j] = expf(v[j] - m); s += v[j]; }
        float inv = 1.f / s;
#pragma unroll
        for (int j = 0; j < SUB_NO; ++j) {
            float w = v[j] * inv;
            o[j * stride + e]  = w;
            tp[e * TSTR + j]   = __float2half(w);
        }
    }

    int f = tid - (E_NO + I_NO);
    if (f >= 0 && f < 40 * T_NO) {
        int row  = f / T_NO;
        int k    = f - row * T_NO;
        int type = row / SUB_NO;
        int s    = row - type * SUB_NO;
        float delta = expf(Dsyn[s * 2 + type]);
        float tau   = expf(Tausyn[s * 2 + type]);
        float w     = expf(Wsyn[s * 2 + type]);
        float tt    = fmaxf((float)k - delta, 0.f) / tau;
        float val   = tt * expf(-tt) * w;
        if (type) val = -val;
        out[OFF_F + row * T_NO + k] = val;
    }

    int p = tid - (E_NO + I_NO + 40 * T_NO);
    if (p >= 0 && p < SUB_NO) {
        g_par[P_GAIN  + p] = expf(Wsub[p]);
        g_par[P_THETA + p] = Theta[p];
#pragma unroll
        for (int type = 0; type < 2; ++type) {
            float delta = expf(Dsyn[p * 2 + type]);
            float tau   = expf(Tausyn[p * 2 + type]);
            float w     = expf(Wsyn[p * 2 + type]);
            float r     = expf(-1.f / tau);
            float B     = w * expf(delta / tau) / tau;
            if (type) B = -B;
            float c1 = (delta > 1.f) ? B * (delta - 1.f) * r : 0.f;
            g_par[(type ? P_RI  : P_RE ) + p] = r;
            g_par[(type ? P_BI  : P_BE ) + p] = B;
            g_par[(type ? P_BDI : P_BDE) + p] = B * delta;
            g_par[(type ? P_C1I : P_C1E) + p] = c1;
        }
    }
    if (tid == N_PREP - 1) g_par[P_VO] = Vo[0];
}

// ---------------- scan + gather primitives ----------------
template<int NFULL, int TAIL, int PF>
__device__ __forceinline__ int row_scan(const float4* __restrict__ Sv, int npad,
                                        ushort* __restrict__ idxb,
                                        int lane, unsigned lt)
{
    constexpr int NT = NFULL + 1;
    const float4 z4 = make_float4(0.f, 0.f, 0.f, 0.f);
    float4 ring[PF];
#pragma unroll
    for (int p = 0; p < PF; ++p) {
        if (p < NT) ring[p] = (p < NFULL || lane < TAIL) ? __ldcs(Sv + p * 32 + lane) : z4;
        else        ring[p] = z4;
    }
    int cnt = 0;
#pragma unroll
    for (int it = 0; it < NT; ++it) {
        float4 v = ring[it % PF];
        if (it + PF < NT)
            ring[it % PF] = ((it + PF) < NFULL || lane < TAIL) ? __ldcs(Sv + (it + PF) * 32 + lane) : z4;
        unsigned m0 = __ballot_sync(0xffffffffu, v.x != 0.f);
        unsigned m1 = __ballot_sync(0xffffffffu, v.y != 0.f);
        unsigned m2 = __ballot_sync(0xffffffffu, v.z != 0.f);
        unsigned m3 = __ballot_sync(0xffffffffu, v.w != 0.f);
        int t0 = __popc(m0), t1 = __popc(m1), t2 = __popc(m2), t3 = __popc(m3);
        int p0 = cnt + __popc(m0 & lt);
        int p1 = cnt + t0 + __popc(m1 & lt);
        int p2 = cnt + t0 + t1 + __popc(m2 & lt);
        int p3 = cnt + t0 + t1 + t2 + __popc(m3 & lt);
        int base = (it * 32 + lane) * 4;
        if (v.x != 0.f) idxb[p0] = (ushort)(base);
        if (v.y != 0.f) idxb[p1] = (ushort)(base + 1);
        if (v.z != 0.f) idxb[p2] = (ushort)(base + 2);
        if (v.w != 0.f) idxb[p3] = (ushort)(base + 3);
        cnt += t0 + t1 + t2 + t3;
    }
    int cpad = (cnt + 7) & ~7;
    if (lane < cpad - cnt) idxb[cnt + lane] = (ushort)npad;  // dummy -> zeroed table row
    return cpad >> 3;
}

__device__ __forceinline__ float gather_h(const uint4* __restrict__ ib, int nk,
                                          const __half* __restrict__ tab, int jj)
{
    float a0 = 0.f, a1 = 0.f;
#pragma unroll 2
    for (int k = 0; k < nk; ++k) {
        uint4 w = ib[k];
        a0 += __half2float(__ldg(tab + ((w.x & 0xffffu) * TSTR + jj)));
        a1 += __half2float(__ldg(tab + ((w.x >> 16)     * TSTR + jj)));
        a0 += __half2float(__ldg(tab + ((w.y & 0xffffu) * TSTR + jj)));
        a1 += __half2float(__ldg(tab + ((w.y >> 16)     * TSTR + jj)));
        a0 += __half2float(__ldg(tab + ((w.z & 0xffffu) * TSTR + jj)));
        a1 += __half2float(__ldg(tab + ((w.z >> 16)     * TSTR + jj)));
        a0 += __half2float(__ldg(tab + ((w.w & 0xffffu) * TSTR + jj)));
        a1 += __half2float(__ldg(tab + ((w.w >> 16)     * TSTR + jj)));
    }
    return a0 + a1;
}

// ---------------- IIR+tree constants ----------------
#define CHU  32
#define NCH  (T_DATA / CHU)    // 625
#define NIT  (PAD + CHU)       // 80, compile-time
#define RD   16
#define PPB  4                 // chunk-quads per block in phase 3

__device__ __forceinline__ float fast_tanh(float x)
{
    x = fminf(fmaxf(x, -15.f), 15.f);
    float e = __expf(2.f * x);
    return __fdividef(e - 1.f, e + 1.f);
}

// ---------------- THE mega-kernel ----------------
#define K2_THREADS 256
#define K2_WARPS   8
#define K2_BLOCKS  (148 * 4)   // exactly one co-resident wave (spin-safe)

__global__ void __launch_bounds__(K2_THREADS, 4)
mega_kernel(const float* __restrict__ Se, const float* __restrict__ Si,
            const float* __restrict__ Craw_e, const float* __restrict__ Craw_i,
            const float* __restrict__ Wsyn, const float* __restrict__ Tausyn,
            const float* __restrict__ Dsyn, const float* __restrict__ Wsub,
            const float* __restrict__ Vo, const float* __restrict__ Theta,
            float* __restrict__ out)
{
    __shared__ __align__(16) ushort idx_s[K2_WARPS][272];
    __shared__ float syn2[PPB][2][CHU][21];

    // ---------- phase 0: prep slice ----------
    int gtid = blockIdx.x * K2_THREADS + threadIdx.x;
    if (gtid < N_PREP)
        do_prep(gtid, Craw_e, Craw_i, Wsyn, Tausyn, Dsyn, Wsub, Vo, Theta, out);
    __threadfence();
    __syncthreads();
    if (threadIdx.x == 0) atomicAdd(&g_A, 1);

    // ---------- phase 1: scan + gather (round-9 ordering) ----------
    int warp = threadIdx.x >> 5;
    int lane = threadIdx.x & 31;
    unsigned lt = (1u << lane) - 1u;
    int jj = (lane < SUB_NO) ? lane : 0;
    ushort* idxb = idx_s[warp];

    int gwarp = blockIdx.x * K2_WARPS + warp;
    bool ready = false;

    for (int row = gwarp; row < T_DATA; row += K2_BLOCKS * K2_WARPS) {
        int enk = row_scan<15, 20, 5>((const float4*)(Se + (size_t)row * E_NO), E_NO,
                                      idxb, lane, lt);
        __syncwarp();
        if (!ready) {   // wait once until all blocks' prep slices are visible
            while (*(volatile int*)&g_A < K2_BLOCKS) __nanosleep(200);
            __threadfence();
            ready = true;
        }
        float ae = gather_h((const uint4*)idxb, enk, g_TEh, jj);
        __syncwarp();

        int ink = row_scan<3, 29, 3>((const float4*)(Si + (size_t)row * I_NO), I_NO,
                                     idxb, lane, lt);
        __syncwarp();
        float ai = gather_h((const uint4*)idxb, ink, g_TIh, jj);
        __syncwarp();

        if (lane < SUB_NO) {
            g_synZe[(PAD + row) * SUB_NO + lane] = ae;
            g_synZi[(PAD + row) * SUB_NO + lane] = ai;
        }
    }

    // ---------- phase 2: grid-wide completion barrier ----------
    __threadfence();
    __syncthreads();
    if (threadIdx.x == 0) {
        atomicAdd(&g_B, 1);
        while (*(volatile int*)&g_B < K2_BLOCKS) __nanosleep(200);
    }
    __syncthreads();
    __threadfence();

    // ---------- phase 3: IIR + tree (first 157 blocks get work) ----------
    {
        int w    = threadIdx.x >> 6;          // 0..3
        int type = (threadIdx.x >> 5) & 1;
        int tlane = threadIdx.x & 31;
        int chunk = blockIdx.x * PPB + w;

        if (chunk < NCH) {
            if (tlane < SUB_NO) {
                int s = tlane;
                const float* __restrict__ x = (type ? g_synZi : g_synZe) + chunk * CHU * SUB_NO + s;
                float r  = g_par[(type ? P_RI  : P_RE ) + s];
                float B  = g_par[(type ? P_BI  : P_BE ) + s];
                float BD = g_par[(type ? P_BDI : P_BDE) + s];
                float C1 = g_par[(type ? P_C1I : P_C1E) + s];

                float ring[RD];
#pragma unroll
                for (int p = 0; p < RD; ++p) ring[p] = x[p * SUB_NO];

                float s1 = 0.f, s2 = 0.f, xp = 0.f;
#pragma unroll
                for (int k = 0; k < NIT; ++k) {
                    float xv = ring[k % RD];
                    if (k + RD < NIT) ring[k % RD] = x[(k + RD) * SUB_NO];
                    float ns2 = r * (s1 + s2);
                    s1 = fmaf(r, s1, xv);
                    s2 = ns2;
                    if (k >= PAD)
                        syn2[w][type][k - PAD][s] = B * s2 - BD * s1 + BD * xv + C1 * xp;
                    xp = xv;
                }
            }
        }
        __syncthreads();

        if (chunk < NCH && type == 0) {
            int t = chunk * CHU + tlane;
            float syn[SUB_NO];
#pragma unroll
            for (int s = 0; s < SUB_NO; ++s)
                syn[s] = syn2[w][0][tlane][s] + syn2[w][1][tlane][s];

            float gain[SUB_NO], th[SUB_NO];
#pragma unroll
            for (int j = 0; j < SUB_NO; ++j) { gain[j] = g_par[P_GAIN + j]; th[j] = g_par[P_THETA + j]; }

            float sub[SUB_NO];
#pragma unroll
            for (int i = SUB_NO - 1; i >= 0; --i) {
                float v = syn[i] + th[i];
                if (2 * i + 1 < SUB_NO) v = fmaf(gain[2 * i + 1], sub[2 * i + 1], v);
                if (2 * i + 2 < SUB_NO) v = fmaf(gain[2 * i + 2], sub[2 * i + 2], v);
                sub[i] = fast_tanh(v);
            }
            out[t] = fmaf(sub[0], gain[0], g_par[P_VO]);
        }
    }

    // ---------- phase 4: last block out resets the barriers (replay-safe) ----------
    __syncthreads();
    if (threadIdx.x == 0) {
        int old = atomicAdd(&g_C, 1);
        if (old == K2_BLOCKS - 1) {   // no block can still be spinning: all passed g_B
            g_A = 0;
            g_B = 0;
            g_C = 0;
            __threadfence();
        }
    }
}

// ---------------- launch ----------------
extern "C" void kernel_launch(void* const* d_in, const int* in_sizes, int n_in,
                              void* d_out, int out_size)
{
    const float* Se     = (const float*)d_in[0];
    const float* Si     = (const float*)d_in[1];
    const float* Wsyn   = (const float*)d_in[3];
    const float* Tausyn = (const float*)d_in[4];
    const float* Dsyn   = (const float*)d_in[5];
    const float* Wsub   = (const float*)d_in[6];
    const float* Vo     = (const float*)d_in[7];
    const float* Theta  = (const float*)d_in[8];
    const float* Ce     = (const float*)d_in[9];
    const float* Ci     = (const float*)d_in[10];
    float* out = (float*)d_out;

    mega_kernel<<<K2_BLOCKS, K2_THREADS>>>(Se, Si, Ce, Ci, Wsyn, Tausyn, Dsyn,
                                           Wsub, Vo, Theta, out);
}

// round 14
// speedup vs baseline: 1.0313x; 1.0005x over previous
#include <cuda_runtime.h>
#include <cuda_fp16.h>
#include <cstdint>
#include <math.h>

#define SUB_NO 20
#define T_NO 201
#define E_NO 2000
#define I_NO 500
#define T_DATA 20000

// Output layout: concat of (V[20000], out_filters[40*201], C_syn_e[20*2000], C_syn_i[20*500])
#define OFF_F  (T_DATA)                   // 20000
#define OFF_CE (OFF_F + 40 * T_NO)        // 28040
#define OFF_CI (OFF_CE + SUB_NO * E_NO)   // 68040

#define PAD 48      // IIR warm-up: r^48 <= 2e-5 rel; tol is 1e-3

#define NQ_E (E_NO / 4)    // 500 quads
#define NQ_I (I_NO / 4)    // 125
#define NT4_E (NQ_E * 16)  // 8000 subset rows
#define NT4_I (NQ_I * 16)  // 2000
#define NB4   (NT4_E + NT4_I)  // 10000

// ---------------- scratch ----------------
__device__ float  g_Tfe[E_NO * 32];                 // fp32 softmax staging [e][j], stride 32
__device__ float  g_Tfi[I_NO * 32];
__device__ __align__(128) __half g_T4e[NT4_E * 32]; // fp16 subset-sum table [(q*16+code)][j]
__device__ __align__(128) __half g_T4i[NT4_I * 32];
__device__ float g_synZe[(PAD + T_DATA) * SUB_NO];
__device__ float g_synZi[(PAD + T_DATA) * SUB_NO];
__device__ int   g_A = 0;   // stage-A (softmax staging) done
__device__ int   g_B = 0;   // stage-B (subset table) done
__device__ int   g_S = 0;   // spike phase done
__device__ int   g_C = 0;   // exit counter (last block resets all)

// param pack
#define P_GAIN  0
#define P_THETA 32
#define P_RE    64
#define P_BE    96
#define P_BDE   128
#define P_C1E   160
#define P_RI    192
#define P_BI    224
#define P_BDI   256
#define P_C1I   288
#define P_VO    320
__device__ float g_par[336];

#define N_PREP (E_NO + I_NO + 40 * T_NO + SUB_NO + 1)   // 10561

// ---------------- stage A: softmax -> fp32 staging + outputs + params ----------------
__device__ void do_prepA(int tid,
                         const float* __restrict__ Craw_e, const float* __restrict__ Craw_i,
                         const float* __restrict__ Wsyn, const float* __restrict__ Tausyn,
                         const float* __restrict__ Dsyn, const float* __restrict__ Wsub,
                         const float* __restrict__ Vo, const float* __restrict__ Theta,
                         float* __restrict__ out)
{
    if (tid < PAD * SUB_NO) {
        g_synZe[tid] = 0.f;
        g_synZi[tid] = 0.f;
    }

    if (tid < E_NO + I_NO) {
        const float* raw;
        float* o;
        float* tf;
        int stride, e;
        if (tid < E_NO) { raw = Craw_e; o = out + OFF_CE; tf = g_Tfe; stride = E_NO; e = tid; }
        else            { raw = Craw_i; o = out + OFF_CI; tf = g_Tfi; stride = I_NO; e = tid - E_NO; }
        float v[SUB_NO];
        float m = -1e30f;
#pragma unroll
        for (int j = 0; j < SUB_NO; ++j) { v[j] = raw[j * stride + e]; m = fmaxf(m, v[j]); }
        float s = 0.f;
#pragma unroll
        for (int j = 0; j < SUB_NO; ++j) { v[j] = expf(v[j] - m); s += v[j]; }
        float inv = 1.f / s;
#pragma unroll
        for (int j = 0; j < SUB_NO; ++j) {
            float w = v[j] * inv;
            o[j * stride + e] = w;
            tf[e * 32 + j]    = w;
        }
    }

    int f = tid - (E_NO + I_NO);
    if (f >= 0 && f < 40 * T_NO) {
        int row  = f / T_NO;
        int k    = f - row * T_NO;
        int type = row / SUB_NO;
        int s    = row - type * SUB_NO;
        float delta = expf(Dsyn[s * 2 + type]);
        float tau   = expf(Tausyn[s * 2 + type]);
        float w     = expf(Wsyn[s * 2 + type]);
        float tt    = fmaxf((float)k - delta, 0.f) / tau;
        float val   = tt * expf(-tt) * w;
        if (type) val = -val;
        out[OFF_F + row * T_NO + k] = val;
    }

    int p = tid - (E_NO + I_NO + 40 * T_NO);
    if (p >= 0 && p < SUB_NO) {
        g_par[P_GAIN  + p] = expf(Wsub[p]);
        g_par[P_THETA + p] = Theta[p];
#pragma unroll
        for (int type = 0; type < 2; ++type) {
            float delta = expf(Dsyn[p * 2 + type]);
            float tau   = expf(Tausyn[p * 2 + type]);
            float w     = expf(Wsyn[p * 2 + type]);
            float r     = expf(-1.f / tau);
            float B     = w * expf(delta / tau) / tau;
            if (type) B = -B;
            float c1 = (delta > 1.f) ? B * (delta - 1.f) * r : 0.f;
            g_par[(type ? P_RI  : P_RE ) + p] = r;
            g_par[(type ? P_BI  : P_BE ) + p] = B;
            g_par[(type ? P_BDI : P_BDE) + p] = B * delta;
            g_par[(type ? P_C1I : P_C1E) + p] = c1;
        }
    }
    if (tid == N_PREP - 1) g_par[P_VO] = Vo[0];
}

// ---------------- stage B: one subset row (q, code) -> fp16 table ----------------
__device__ void build_t4(int sid)
{
    const float* tf;
    __half* dst;
    int q, code;
    if (sid < NT4_E) { tf = g_Tfe; dst = g_T4e + (size_t)sid * 32; q = sid >> 4; code = sid & 15; }
    else { int s2 = sid - NT4_E; tf = g_Tfi; dst = g_T4i + (size_t)s2 * 32; q = s2 >> 4; code = s2 & 15; }

    float4 a[5];
#pragma unroll
    for (int k = 0; k < 5; ++k) a[k] = make_float4(0.f, 0.f, 0.f, 0.f);
#pragma unroll
    for (int c = 0; c < 4; ++c) {
        if ((code >> c) & 1) {
            const float4* r = (const float4*)(tf + (q * 4 + c) * 32);
#pragma unroll
            for (int k = 0; k < 5; ++k) {
                float4 w = r[k];
                a[k].x += w.x; a[k].y += w.y; a[k].z += w.z; a[k].w += w.w;
            }
        }
    }
    __half2* d2 = (__half2*)dst;
#pragma unroll
    for (int k = 0; k < 5; ++k) {
        d2[2 * k]     = __floats2half2_rn(a[k].x, a[k].y);
        d2[2 * k + 1] = __floats2half2_rn(a[k].z, a[k].w);
    }
}

// ---------------- quad scan: one ballot/popc per float4 ----------------
template<int NFULL, int TAIL, int PF>
__device__ __forceinline__ int row_scan_q(const float4* __restrict__ Sv,
                                          ushort* __restrict__ idxb,
                                          int lane, unsigned lt)
{
    constexpr int NT = NFULL + 1;
    const float4 z4 = make_float4(0.f, 0.f, 0.f, 0.f);
    float4 ring[PF];
#pragma unroll
    for (int p = 0; p < PF; ++p) {
        if (p < NT) ring[p] = (p < NFULL || lane < TAIL) ? __ldcs(Sv + p * 32 + lane) : z4;
        else        ring[p] = z4;
    }
    int cnt = 0;
#pragma unroll
    for (int it = 0; it < NT; ++it) {
        float4 v = ring[it % PF];
        if (it + PF < NT)
            ring[it % PF] = ((it + PF) < NFULL || lane < TAIL) ? __ldcs(Sv + (it + PF) * 32 + lane) : z4;
        // code = x + 2y + 4z + 8w  (exact: spikes are {0,1}) — FMA pipe, 1 ballot total
        float cf = fmaf(2.f, v.y, v.x);
        cf = fmaf(4.f, v.z, cf);
        cf = fmaf(8.f, v.w, cf);
        int code = __float2int_rn(cf);
        unsigned m = __ballot_sync(0xffffffffu, code != 0);
        int pref = __popc(m & lt);
        if (code) idxb[cnt + pref] = (ushort)((((it * 32) + lane) << 4) | code);
        cnt += __popc(m);
    }
    int cpad = (cnt + 7) & ~7;
    if (lane < cpad - cnt) idxb[cnt + lane] = 0;   // dummy -> zero row (q0, code0)
    return cpad >> 3;
}

// subset-table gather: one fp16 load + add per nonzero quad
__device__ __forceinline__ float gather_q(const uint4* __restrict__ ib, int nk,
                                          const __half* __restrict__ tab, int jj)
{
    float a0 = 0.f, a1 = 0.f;
#pragma unroll 2
    for (int k = 0; k < nk; ++k) {
        uint4 w = ib[k];
        a0 += __half2float(__ldg(tab + (w.x & 0xffffu) * 32 + jj));
        a1 += __half2float(__ldg(tab + (w.x >> 16)     * 32 + jj));
        a0 += __half2float(__ldg(tab + (w.y & 0xffffu) * 32 + jj));
        a1 += __half2float(__ldg(tab + (w.y >> 16)     * 32 + jj));
        a0 += __half2float(__ldg(tab + (w.z & 0xffffu) * 32 + jj));
        a1 += __half2float(__ldg(tab + (w.z >> 16)     * 32 + jj));
        a0 += __half2float(__ldg(tab + (w.w & 0xffffu) * 32 + jj));
        a1 += __half2float(__ldg(tab + (w.w >> 16)     * 32 + jj));
    }
    return a0 + a1;
}

// ---------------- IIR+tree constants ----------------
#define CHU  32
#define NCH  (T_DATA / CHU)    // 625
#define NIT  (PAD + CHU)       // 80, compile-time
#define RD   16
#define PPB  4

__device__ __forceinline__ float fast_tanh(float x)
{
    x = fminf(fmaxf(x, -15.f), 15.f);
    float e = __expf(2.f * x);
    return __fdividef(e - 1.f, e + 1.f);
}

// ---------------- THE mega-kernel ----------------
#define K2_THREADS 256
#define K2_WARPS   8
#define K2_BLOCKS  (148 * 4)   // exactly one co-resident wave (spin-safe)

__global__ void __launch_bounds__(K2_THREADS, 4)
mega_kernel(const float* __restrict__ Se, const float* __restrict__ Si,
            const float* __restrict__ Craw_e, const float* __restrict__ Craw_i,
            const float* __restrict__ Wsyn, const float* __restrict__ Tausyn,
            const float* __restrict__ Dsyn, const float* __restrict__ Wsub,
            const float* __restrict__ Vo, const float* __restrict__ Theta,
            float* __restrict__ out)
{
    __shared__ __align__(16) ushort idx_s[K2_WARPS][272];
    __shared__ float syn2[PPB][2][CHU][21];

    // ---------- phase 0: stage-A prep slice ----------
    int gtid = blockIdx.x * K2_THREADS + threadIdx.x;
    if (gtid < N_PREP)
        do_prepA(gtid, Craw_e, Craw_i, Wsyn, Tausyn, Dsyn, Wsub, Vo, Theta, out);
    __threadfence();
    __syncthreads();
    if (threadIdx.x == 0) atomicAdd(&g_A, 1);

    // ---------- phase 1: quad scan + subset gather ----------
    int warp = threadIdx.x >> 5;
    int lane = threadIdx.x & 31;
    unsigned lt = (1u << lane) - 1u;
    int jj = (lane < SUB_NO) ? lane : 0;
    ushort* idxb = idx_s[warp];

    int gwarp = blockIdx.x * K2_WARPS + warp;
    bool ready = false;

    for (int row = gwarp; row < T_DATA; row += K2_BLOCKS * K2_WARPS) {
        int enk = row_scan_q<15, 20, 5>((const float4*)(Se + (size_t)row * E_NO), idxb, lane, lt);
        __syncwarp();

        if (!ready) {
            // all warps reach here exactly once (first iteration)
            __syncthreads();
            if (threadIdx.x == 0)
                while (*(volatile int*)&g_A < K2_BLOCKS) __nanosleep(100);
            __syncthreads();
            __threadfence();
            if (gtid < NB4) build_t4(gtid);        // stage B: subset table rows
            __threadfence();
            __syncthreads();
            if (threadIdx.x == 0) {
                atomicAdd(&g_B, 1);
                while (*(volatile int*)&g_B < K2_BLOCKS) __nanosleep(100);
            }
            __syncthreads();
            __threadfence();
            ready = true;
        }

        float ae = gather_q((const uint4*)idxb, enk, g_T4e, jj);
        __syncwarp();

        int ink = row_scan_q<3, 29, 3>((const float4*)(Si + (size_t)row * I_NO), idxb, lane, lt);
        __syncwarp();
        float ai = gather_q((const uint4*)idxb, ink, g_T4i, jj);
        __syncwarp();

        if (lane < SUB_NO) {
            g_synZe[(PAD + row) * SUB_NO + lane] = ae;
            g_synZi[(PAD + row) * SUB_NO + lane] = ai;
        }
    }

    // ---------- phase 2: grid-wide completion barrier ----------
    __threadfence();
    __syncthreads();
    if (threadIdx.x == 0) {
        atomicAdd(&g_S, 1);
        while (*(volatile int*)&g_S < K2_BLOCKS) __nanosleep(200);
    }
    __syncthreads();
    __threadfence();

    // ---------- phase 3: IIR + tree (first 157 blocks get work) ----------
    {
        int w    = threadIdx.x >> 6;
        int type = (threadIdx.x >> 5) & 1;
        int tlane = threadIdx.x & 31;
        int chunk = blockIdx.x * PPB + w;

        if (chunk < NCH && tlane < SUB_NO) {
            int s = tlane;
            const float* __restrict__ x = (type ? g_synZi : g_synZe) + chunk * CHU * SUB_NO + s;
            float r  = g_par[(type ? P_RI  : P_RE ) + s];
            float B  = g_par[(type ? P_BI  : P_BE ) + s];
            float BD = g_par[(type ? P_BDI : P_BDE) + s];
            float C1 = g_par[(type ? P_C1I : P_C1E) + s];

            float ring[RD];
#pragma unroll
            for (int p = 0; p < RD; ++p) ring[p] = x[p * SUB_NO];

            float s1 = 0.f, s2 = 0.f, xp = 0.f;
#pragma unroll
            for (int k = 0; k < NIT; ++k) {
                float xv = ring[k % RD];
                if (k + RD < NIT) ring[k % RD] = x[(k + RD) * SUB_NO];
                float ns2 = r * (s1 + s2);
                s1 = fmaf(r, s1, xv);
                s2 = ns2;
                if (k >= PAD)
                    syn2[w][type][k - PAD][s] = B * s2 - BD * s1 + BD * xv + C1 * xp;
                xp = xv;
            }
        }
        __syncthreads();

        if (chunk < NCH && type == 0) {
            int t = chunk * CHU + tlane;
            float syn[SUB_NO];
#pragma unroll
            for (int s = 0; s < SUB_NO; ++s)
                syn[s] = syn2[w][0][tlane][s] + syn2[w][1][tlane][s];

            float gain[SUB_NO], th[SUB_NO];
#pragma unroll
            for (int j = 0; j < SUB_NO; ++j) { gain[j] = g_par[P_GAIN + j]; th[j] = g_par[P_THETA + j]; }

            float sub[SUB_NO];
#pragma unroll
            for (int i = SUB_NO - 1; i >= 0; --i) {
                float vv = syn[i] + th[i];
                if (2 * i + 1 < SUB_NO) vv = fmaf(gain[2 * i + 1], sub[2 * i + 1], vv);
                if (2 * i + 2 < SUB_NO) vv = fmaf(gain[2 * i + 2], sub[2 * i + 2], vv);
                sub[i] = fast_tanh(vv);
            }
            out[t] = fmaf(sub[0], gain[0], g_par[P_VO]);
        }
    }

    // ---------- phase 4: last block out resets the barriers (replay-safe) ----------
    __syncthreads();
    if (threadIdx.x == 0) {
        int old = atomicAdd(&g_C, 1);
        if (old == K2_BLOCKS - 1) {   // no block can still be spinning: all passed g_S
            g_A = 0;
            g_B = 0;
            g_S = 0;
            g_C = 0;
            __threadfence();
        }
    }
}

// ---------------- launch ----------------
extern "C" void kernel_launch(void* const* d_in, const int* in_sizes, int n_in,
                              void* d_out, int out_size)
{
    const float* Se     = (const float*)d_in[0];
    const float* Si     = (const float*)d_in[1];
    const float* Wsyn   = (const float*)d_in[3];
    const float* Tausyn = (const float*)d_in[4];
    const float* Dsyn   = (const float*)d_in[5];
    const float* Wsub   = (const float*)d_in[6];
    const float* Vo     = (const float*)d_in[7];
    const float* Theta  = (const float*)d_in[8];
    const float* Ce     = (const float*)d_in[9];
    const float* Ci     = (const float*)d_in[10];
    float* out = (float*)d_out;

    mega_kernel<<<K2_BLOCKS, K2_THREADS>>>(Se, Si, Ce, Ci, Wsyn, Tausyn, Dsyn,
                                           Wsub, Vo, Theta, out);
}